// round 7
// baseline (speedup 1.0000x reference)
#include <cuda_runtime.h>
#include <cuda_fp16.h>

// PatternDetector: B=131072 rows x L=256 int32 in [0,40). Output Bx4 f32.
//
// Stable "nonzeros-first" argsort preserves order -> all features are
// functions of consecutive-nonzero pairs -> single forward scan per row.
// dec = (n-1) - rep - inc.
//
// R7 = R5 structure (two 32-elem chains per thread SIMD'd into one half2
// recurrence; values carried as half 1024+v, bits 0x6400|v, exact) with a
// mask-based inner loop:
//   - set.{eq,gt,ne}.u32.f16x2 -> 0xFFFF/0 per-half masks (1 HSET2 each)
//   - prev blends via single LOP3: p = (v & m) | (p & ~m)   (4-cyc chain)
//   - counters as packed u16x2 via __vsub2(acc, mask)       (mask == -1)
// Sentinel 127 -> 1151.0: never equal to any biased v (<=1063), never less.

constexpr int TPB     = 256;
constexpr int RPB     = 64;
constexpr int L_LEN   = 256;
constexpr int CSTRIDE = 80;    // 64B chunk in 20-word slot: LDS.128 conflict-free

__device__ __forceinline__ unsigned heq2_mask(unsigned a, unsigned b) {
    unsigned d; asm("set.eq.u32.f16x2 %0, %1, %2;" : "=r"(d) : "r"(a), "r"(b)); return d;
}
__device__ __forceinline__ unsigned hgt2_mask(unsigned a, unsigned b) {
    unsigned d; asm("set.gt.u32.f16x2 %0, %1, %2;" : "=r"(d) : "r"(a), "r"(b)); return d;
}
__device__ __forceinline__ unsigned hne2_mask(unsigned a, unsigned b) {
    unsigned d; asm("set.ne.u32.f16x2 %0, %1, %2;" : "=r"(d) : "r"(a), "r"(b)); return d;
}

// branchless "last two nonzeros" of a 4-byte word (ascending position order)
__device__ __forceinline__ void last2nz_word(unsigned w, int& p1, int& p2, int& cnt)
{
    p1 = 0; p2 = 0; cnt = 0;
    #pragma unroll
    for (int k = 0; k < 4; ++k) {
        int v = (w >> (8 * k)) & 0xff;
        bool nz = (v != 0);
        p2 = nz ? p1 : p2;
        p1 = nz ? v  : p1;
        cnt += nz;
    }
}

__global__ void __launch_bounds__(TPB, 5) pattern_kernel(
    const int4* __restrict__ x4, float4* __restrict__ out)
{
    __shared__ unsigned char s[TPB * CSTRIDE];   // 20480 B
    const int tid = threadIdx.x;

    // ---- Stage: coalesced gmem -> byte-packed smem ----
    const int4* src = x4 + (long long)blockIdx.x * (RPB * L_LEN / 4);
    #pragma unroll
    for (int it = 0; it < 16; ++it) {
        int idx = it * TPB + tid;
        int4 v  = src[idx];
        unsigned packed = (unsigned)v.x | ((unsigned)v.y << 8)
                        | ((unsigned)v.z << 16) | ((unsigned)v.w << 24);
        *(unsigned*)&s[(idx >> 4) * CSTRIDE + (idx & 15) * 4] = packed;
    }
    __syncthreads();

    const int c         = tid & 3;      // chunk within row
    const int row_chunk = tid & ~3;

    // ---- Preload phase 1 ----
    const uint4* chunk = (const uint4*)&s[tid * CSTRIDE];
    uint4 q0 = chunk[0];
    uint4 q2 = chunk[2];

    // ---- Chain A init: last 2 nonzeros before element c*64 ----
    int a1 = 127, a2 = 127;
    if (c) {
        unsigned w = *(const unsigned*)&s[(tid - 1) * CSTRIDE + 60];
        int p1, p2, cnt;
        last2nz_word(w, p1, p2, cnt);
        if (cnt >= 2) { a1 = p1; a2 = p2; }
        else {
            int j = c * 64 - 1, found = 0;
            while (j >= 0 && found < 2) {
                int v = s[(row_chunk + (j >> 6)) * CSTRIDE + (j & 63)];
                if (v) { if (!found) a1 = v; else a2 = v; ++found; }
                --j;
            }
        }
    }

    // ---- Preload phase 2 ----
    uint4 q1 = chunk[1];
    uint4 q3 = chunk[3];

    // ---- Chain B init: last 2 nonzeros before element c*64+32 ----
    int b1 = 127, b2 = 127;
    {
        int p1, p2, cnt;
        last2nz_word(q1.w, p1, p2, cnt);   // elements 28..31 of this chunk
        if (cnt >= 2) { b1 = p1; b2 = p2; }
        else {
            int j = c * 64 + 31, found = 0;
            while (j >= 0 && found < 2) {
                int v = s[(row_chunk + (j >> 6)) * CSTRIDE + (j & 63)];
                if (v) { if (!found) b1 = v; else b2 = v; ++found; }
                --j;
            }
        }
    }

    // ---- SWAR state: low half = chain A, high half = chain B ----
    const unsigned BIAS = 0x64006400u;    // half2 {1024, 1024}
    const unsigned BMSK = 0x00FF00FFu;
    unsigned p1h = (unsigned)(0x6400 | a1) | ((unsigned)(0x6400 | b1) << 16);
    unsigned p2h = (unsigned)(0x6400 | a2) | ((unsigned)(0x6400 | b2) << 16);
    unsigned accR = 0, accI = 0, accP = 0, accN = 0;   // packed u16x2 counters

    unsigned WA[8] = {q0.x, q0.y, q0.z, q0.w, q1.x, q1.y, q1.z, q1.w};
    unsigned WB[8] = {q2.x, q2.y, q2.z, q2.w, q3.x, q3.y, q3.z, q3.w};

    #pragma unroll
    for (int w = 0; w < 8; ++w) {
        unsigned wa = WA[w], wb = WB[w];
        #pragma unroll
        for (int k = 0; k < 4; ++k) {
            // interleave byte k of wa (chain A) and wb (chain B), bias to half
            unsigned pr = __byte_perm(wa, wb, 0x0400 + k * 0x0101);
            unsigned v  = (pr & BMSK) | BIAS;            // {1024+va, 1024+vb}

            unsigned mR = heq2_mask(v, p1h);
            unsigned mI = hgt2_mask(v, p1h);
            unsigned mP = heq2_mask(v, p2h);
            unsigned mN = hne2_mask(v, BIAS);            // nonzero mask

            accR = __vsub2(accR, mR);                    // mask == -1 per lane
            accI = __vsub2(accI, mI);
            accP = __vsub2(accP, mP);
            accN = __vsub2(accN, mN);

            p2h = (p1h & mN) | (p2h & ~mN);              // single LOP3 each
            p1h = (v   & mN) | (p1h & ~mN);
        }
    }

    // ---- Reduce across the 4 chunk lanes (u16 lanes, max 256: no overflow) ----
    #pragma unroll
    for (int m = 1; m <= 2; m <<= 1) {
        accR = __vadd2(accR, __shfl_xor_sync(0xffffffffu, accR, m));
        accI = __vadd2(accI, __shfl_xor_sync(0xffffffffu, accI, m));
        accP = __vadd2(accP, __shfl_xor_sync(0xffffffffu, accP, m));
        accN = __vadd2(accN, __shfl_xor_sync(0xffffffffu, accN, m));
    }

    if (c == 0) {
        int REP = (int)(accR & 0xffffu) + (int)(accR >> 16);
        int INC = (int)(accI & 0xffffu) + (int)(accI >> 16);
        int PER = (int)(accP & 0xffffu) + (int)(accP >> 16);
        int N   = (int)(accN & 0xffffu) + (int)(accN >> 16);
        float o0 = 0.f, o1 = 0.f, o2 = 0.f, o3 = 0.f;
        if (N > 1) {
            int DEC  = (N - 1) - REP - INC;
            float d1 = 1.0f / (float)(N - 1);
            o0 = (float)REP * d1;
            o1 = (float)INC * d1;
            o2 = (float)DEC * d1;
            if (N >= 4) o3 = (float)PER / (float)(N - 2);
        }
        out[(long long)blockIdx.x * RPB + (tid >> 2)] =
            make_float4(o0, o1, o2, o3);
    }
}

extern "C" void kernel_launch(void* const* d_in, const int* in_sizes, int n_in,
                              void* d_out, int out_size)
{
    const int4* x = (const int4*)d_in[0];
    float4* out   = (float4*)d_out;
    const int total_elems = in_sizes[0];      // B * L
    const int nrows  = total_elems / L_LEN;   // 131072
    const int blocks = nrows / RPB;           // 2048
    pattern_kernel<<<blocks, TPB>>>(x, out);
}

// round 9
// speedup vs baseline: 1.0088x; 1.0088x over previous
#include <cuda_runtime.h>
#include <cuda_fp16.h>

// PatternDetector: B=131072 rows x L=256 int32 in [0,40). Output Bx4 f32.
//
// Stable "nonzeros-first" argsort preserves order -> all features are
// functions of consecutive-nonzero pairs -> single forward scan per row.
// dec = (n-1) - rep - inc.
//
// R9 = R8 with the chain-B init fixed: the fast-path word is the one holding
// elements 28..31 (byte offset 28 in the chunk slot), the 4 elements that
// precede chain B's start at element 32. (R8 wrongly read byte 60 =
// elements 60..63.)
//
// Inner loop (from R7): half2 SIMD of two 32-elem chains, values as half
// 1024+v = bits 0x6400|v; compares -> 0xFFFF masks via set.*.u32.f16x2;
// prev blends = single LOP3; counters = packed u16x2 via vsub2.
// Shape: 128-thread / 32-row blocks, 10KB smem, 12 blocks/SM.

constexpr int TPB     = 128;
constexpr int RPB     = 32;
constexpr int L_LEN   = 256;
constexpr int CSTRIDE = 80;    // 64B chunk in 20-word slot: LDS.128 conflict-free

__device__ __forceinline__ unsigned heq2_mask(unsigned a, unsigned b) {
    unsigned d; asm("set.eq.u32.f16x2 %0, %1, %2;" : "=r"(d) : "r"(a), "r"(b)); return d;
}
__device__ __forceinline__ unsigned hgt2_mask(unsigned a, unsigned b) {
    unsigned d; asm("set.gt.u32.f16x2 %0, %1, %2;" : "=r"(d) : "r"(a), "r"(b)); return d;
}
__device__ __forceinline__ unsigned hne2_mask(unsigned a, unsigned b) {
    unsigned d; asm("set.ne.u32.f16x2 %0, %1, %2;" : "=r"(d) : "r"(a), "r"(b)); return d;
}

// branchless "last two nonzeros" of a 4-byte word (ascending position order)
__device__ __forceinline__ void last2nz_word(unsigned w, int& p1, int& p2, int& cnt)
{
    p1 = 0; p2 = 0; cnt = 0;
    #pragma unroll
    for (int k = 0; k < 4; ++k) {
        int v = (w >> (8 * k)) & 0xff;
        bool nz = (v != 0);
        p2 = nz ? p1 : p2;
        p1 = nz ? v  : p1;
        cnt += nz;
    }
}

__global__ void __launch_bounds__(TPB, 12) pattern_kernel(
    const int4* __restrict__ x4, float4* __restrict__ out)
{
    __shared__ unsigned char s[TPB * CSTRIDE];   // 10240 B
    const int tid = threadIdx.x;

    // ---- Stage: coalesced gmem -> byte-packed smem (3 PRMT pack) ----
    const int4* src = x4 + (long long)blockIdx.x * (RPB * L_LEN / 4);
    #pragma unroll
    for (int it = 0; it < 16; ++it) {
        int idx = it * TPB + tid;
        int4 v  = src[idx];
        unsigned lo = __byte_perm((unsigned)v.x, (unsigned)v.y, 0x0040);
        unsigned hi = __byte_perm((unsigned)v.z, (unsigned)v.w, 0x0040);
        unsigned packed = __byte_perm(lo, hi, 0x5410);
        *(unsigned*)&s[(idx >> 4) * CSTRIDE + (idx & 15) * 4] = packed;
    }
    __syncthreads();

    const int c         = tid & 3;      // chunk within row
    const int row_chunk = tid & ~3;

    // ---- Chain A init: last 2 nonzeros before element c*64 ----
    // fast path: last word of the PREVIOUS chunk (its elements 60..63)
    int a1 = 127, a2 = 127;
    if (c) {
        unsigned w = *(const unsigned*)&s[(tid - 1) * CSTRIDE + 60];
        int p1, p2, cnt;
        last2nz_word(w, p1, p2, cnt);
        if (cnt >= 2) { a1 = p1; a2 = p2; }
        else {
            int j = c * 64 - 1, found = 0;
            while (j >= 0 && found < 2) {
                int v = s[(row_chunk + (j >> 6)) * CSTRIDE + (j & 63)];
                if (v) { if (!found) a1 = v; else a2 = v; ++found; }
                --j;
            }
        }
    }

    // ---- Chain B init: last 2 nonzeros before element c*64+32 ----
    // fast path: word holding elements 28..31 of THIS chunk = byte offset 28
    int b1 = 127, b2 = 127;
    {
        unsigned w = *(const unsigned*)&s[tid * CSTRIDE + 28];
        int p1, p2, cnt;
        last2nz_word(w, p1, p2, cnt);
        if (cnt >= 2) { b1 = p1; b2 = p2; }
        else {
            int j = c * 64 + 31, found = 0;
            while (j >= 0 && found < 2) {
                int v = s[(row_chunk + (j >> 6)) * CSTRIDE + (j & 63)];
                if (v) { if (!found) b1 = v; else b2 = v; ++found; }
                --j;
            }
        }
    }

    // ---- SWAR state: low half = chain A, high half = chain B ----
    const unsigned BIAS = 0x64006400u;    // half2 {1024, 1024}
    const unsigned BMSK = 0x00FF00FFu;
    unsigned p1h = (unsigned)(0x6400 | a1) | ((unsigned)(0x6400 | b1) << 16);
    unsigned p2h = (unsigned)(0x6400 | a2) | ((unsigned)(0x6400 | b2) << 16);
    unsigned accR = 0, accI = 0, accP = 0, accN = 0;   // packed u16x2 counters

    const uint4* chunk = (const uint4*)&s[tid * CSTRIDE];

    // Two half-passes: only one (qa, qb) pair live at a time (register diet).
    // Chain A order: chunk[0] (elems 0-15) then chunk[1] (16-31).
    // Chain B order: chunk[2] (elems 32-47) then chunk[3] (48-63).
    #pragma unroll
    for (int h = 0; h < 2; ++h) {
        uint4 qa = chunk[h];
        uint4 qb = chunk[2 + h];
        unsigned WAh[4] = {qa.x, qa.y, qa.z, qa.w};
        unsigned WBh[4] = {qb.x, qb.y, qb.z, qb.w};
        #pragma unroll
        for (int w = 0; w < 4; ++w) {
            unsigned wa = WAh[w], wb = WBh[w];
            #pragma unroll
            for (int k = 0; k < 4; ++k) {
                unsigned pr = __byte_perm(wa, wb, 0x0400 + k * 0x0101);
                unsigned v  = (pr & BMSK) | BIAS;        // {1024+va, 1024+vb}

                unsigned mR = heq2_mask(v, p1h);
                unsigned mI = hgt2_mask(v, p1h);
                unsigned mP = heq2_mask(v, p2h);
                unsigned mN = hne2_mask(v, BIAS);        // nonzero mask

                accR = __vsub2(accR, mR);                // mask == -1 per lane
                accI = __vsub2(accI, mI);
                accP = __vsub2(accP, mP);
                accN = __vsub2(accN, mN);

                p2h = (p1h & mN) | (p2h & ~mN);          // single LOP3 each
                p1h = (v   & mN) | (p1h & ~mN);
            }
        }
    }

    // ---- Reduce across the 4 chunk lanes (u16 lanes, max 256: no overflow) ----
    #pragma unroll
    for (int m = 1; m <= 2; m <<= 1) {
        accR = __vadd2(accR, __shfl_xor_sync(0xffffffffu, accR, m));
        accI = __vadd2(accI, __shfl_xor_sync(0xffffffffu, accI, m));
        accP = __vadd2(accP, __shfl_xor_sync(0xffffffffu, accP, m));
        accN = __vadd2(accN, __shfl_xor_sync(0xffffffffu, accN, m));
    }

    if (c == 0) {
        int REP = (int)(accR & 0xffffu) + (int)(accR >> 16);
        int INC = (int)(accI & 0xffffu) + (int)(accI >> 16);
        int PER = (int)(accP & 0xffffu) + (int)(accP >> 16);
        int N   = (int)(accN & 0xffffu) + (int)(accN >> 16);
        float o0 = 0.f, o1 = 0.f, o2 = 0.f, o3 = 0.f;
        if (N > 1) {
            int DEC  = (N - 1) - REP - INC;
            float d1 = 1.0f / (float)(N - 1);
            o0 = (float)REP * d1;
            o1 = (float)INC * d1;
            o2 = (float)DEC * d1;
            if (N >= 4) o3 = (float)PER / (float)(N - 2);
        }
        out[(long long)blockIdx.x * RPB + (tid >> 2)] =
            make_float4(o0, o1, o2, o3);
    }
}

extern "C" void kernel_launch(void* const* d_in, const int* in_sizes, int n_in,
                              void* d_out, int out_size)
{
    const int4* x = (const int4*)d_in[0];
    float4* out   = (float4*)d_out;
    const int total_elems = in_sizes[0];      // B * L
    const int nrows  = total_elems / L_LEN;   // 131072
    const int blocks = nrows / RPB;           // 4096
    pattern_kernel<<<blocks, TPB>>>(x, out);
}

// round 10
// speedup vs baseline: 1.0824x; 1.0730x over previous
#include <cuda_runtime.h>
#include <cuda_fp16.h>

// PatternDetector: B=131072 rows x L=256 int32 in [0,40). Output Bx4 f32.
//
// Stable "nonzeros-first" argsort preserves order -> all features are
// functions of consecutive-nonzero pairs -> single forward scan per row.
// dec = (n-1) - rep - inc.
//
// R10: persistent blocks with a 2-stage cp.async (LDGSTS) pipeline.
// gmem -> raw smem happens asynchronously while the previous tile is
// repacked (raw int32 -> packed bytes, conflict-free) and scanned.
// Scan inner loop = R9 (passing): half2 SIMD of two 32-elem chains,
// values as half 1024+v (bits 0x6400|v); compares -> 0xFFFF masks via
// set.*.u32.f16x2; prev blends = single LOP3; counters packed u16x2.

constexpr int TPB        = 64;     // threads per block (= chunks per tile)
constexpr int ROWS_TILE  = 16;     // rows per tile
constexpr int L_LEN      = 256;
constexpr int TILE_INT4  = ROWS_TILE * L_LEN / 4;   // 1024
constexpr int RAW_BYTES  = TILE_INT4 * 16;          // 16384
constexpr int CSTRIDE    = 80;     // 64B chunk in 20-word slot (conflict-free)
constexpr int CHUNKS     = ROWS_TILE * 4;           // 64
constexpr int PACKED_B   = CHUNKS * CSTRIDE;        // 5120
constexpr int SMEM_TOTAL = 2 * RAW_BYTES + PACKED_B; // 37888 (<48KB)
constexpr int GRID       = 912;    // ~152 SM x 6 blocks

__device__ __forceinline__ unsigned heq2_mask(unsigned a, unsigned b) {
    unsigned d; asm("set.eq.u32.f16x2 %0, %1, %2;" : "=r"(d) : "r"(a), "r"(b)); return d;
}
__device__ __forceinline__ unsigned hgt2_mask(unsigned a, unsigned b) {
    unsigned d; asm("set.gt.u32.f16x2 %0, %1, %2;" : "=r"(d) : "r"(a), "r"(b)); return d;
}
__device__ __forceinline__ unsigned hne2_mask(unsigned a, unsigned b) {
    unsigned d; asm("set.ne.u32.f16x2 %0, %1, %2;" : "=r"(d) : "r"(a), "r"(b)); return d;
}

__device__ __forceinline__ void last2nz_word(unsigned w, int& p1, int& p2, int& cnt)
{
    p1 = 0; p2 = 0; cnt = 0;
    #pragma unroll
    for (int k = 0; k < 4; ++k) {
        int v = (w >> (8 * k)) & 0xff;
        bool nz = (v != 0);
        p2 = nz ? p1 : p2;
        p1 = nz ? v  : p1;
        cnt += nz;
    }
}

// issue one tile's worth of cp.async.cg (16B each) + commit the group
__device__ __forceinline__ void issue_tile(const char* gsrc, unsigned smem_dst)
{
    #pragma unroll
    for (int i = 0; i < TILE_INT4 / TPB; ++i) {          // 16 per thread
        int idx = i * TPB + (int)threadIdx.x;
        unsigned dst = smem_dst + idx * 16;
        asm volatile("cp.async.cg.shared.global [%0], [%1], 16;"
                     :: "r"(dst), "l"(gsrc + (size_t)idx * 16));
    }
    asm volatile("cp.async.commit_group;" ::: "memory");
}

__global__ void __launch_bounds__(TPB, 6) pattern_kernel(
    const int4* __restrict__ x4, float4* __restrict__ out, int total_tiles)
{
    extern __shared__ unsigned char smem[];
    unsigned raw_smem = (unsigned)__cvta_generic_to_shared(smem);
    unsigned char* packed = smem + 2 * RAW_BYTES;

    const int tid = threadIdx.x;
    const int c         = tid & 3;      // chunk within row
    const int row_chunk = tid & ~3;
    const unsigned BIAS = 0x64006400u;  // half2 {1024, 1024}
    const unsigned BMSK = 0x00FF00FFu;

    int t = blockIdx.x;
    if (t < total_tiles)
        issue_tile((const char*)(x4 + (long long)t * TILE_INT4), raw_smem);

    int buf = 0;
    for (; t < total_tiles; t += GRID, buf ^= 1) {
        // ---- pipeline: issue next tile, wait for current ----
        int tn = t + GRID;
        if (tn < total_tiles) {
            issue_tile((const char*)(x4 + (long long)tn * TILE_INT4),
                       raw_smem + (buf ^ 1) * RAW_BYTES);
            asm volatile("cp.async.wait_group 1;" ::: "memory");
        } else {
            asm volatile("cp.async.wait_group 0;" ::: "memory");
        }
        __syncthreads();   // raw[buf] visible to all; prev scan of packed done

        // ---- repack: raw int32 -> packed bytes (both sides conflict-free) ----
        const int4* rp = (const int4*)(smem + buf * RAW_BYTES);
        #pragma unroll
        for (int i = 0; i < TILE_INT4 / TPB; ++i) {
            int idx = i * TPB + tid;
            int4 v  = rp[idx];
            unsigned lo = __byte_perm((unsigned)v.x, (unsigned)v.y, 0x0040);
            unsigned hi = __byte_perm((unsigned)v.z, (unsigned)v.w, 0x0040);
            unsigned pk = __byte_perm(lo, hi, 0x5410);
            *(unsigned*)&packed[(idx >> 4) * CSTRIDE + (idx & 15) * 4] = pk;
        }
        __syncthreads();

        // ---- chain inits (peek in packed buffer) ----
        int a1 = 127, a2 = 127;
        if (c) {
            unsigned w = *(const unsigned*)&packed[(tid - 1) * CSTRIDE + 60];
            int p1, p2, cnt;
            last2nz_word(w, p1, p2, cnt);
            if (cnt >= 2) { a1 = p1; a2 = p2; }
            else {
                int j = c * 64 - 1, found = 0;
                while (j >= 0 && found < 2) {
                    int v = packed[(row_chunk + (j >> 6)) * CSTRIDE + (j & 63)];
                    if (v) { if (!found) a1 = v; else a2 = v; ++found; }
                    --j;
                }
            }
        }
        int b1 = 127, b2 = 127;
        {
            // word holding elements 28..31 of THIS chunk = byte offset 28
            unsigned w = *(const unsigned*)&packed[tid * CSTRIDE + 28];
            int p1, p2, cnt;
            last2nz_word(w, p1, p2, cnt);
            if (cnt >= 2) { b1 = p1; b2 = p2; }
            else {
                int j = c * 64 + 31, found = 0;
                while (j >= 0 && found < 2) {
                    int v = packed[(row_chunk + (j >> 6)) * CSTRIDE + (j & 63)];
                    if (v) { if (!found) b1 = v; else b2 = v; ++found; }
                    --j;
                }
            }
        }

        // ---- SWAR scan: low half = chain A (elems 0-31), high = B (32-63) ----
        unsigned p1h = (unsigned)(0x6400 | a1) | ((unsigned)(0x6400 | b1) << 16);
        unsigned p2h = (unsigned)(0x6400 | a2) | ((unsigned)(0x6400 | b2) << 16);
        unsigned accR = 0, accI = 0, accP = 0, accN = 0;

        const uint4* chunk = (const uint4*)&packed[tid * CSTRIDE];
        #pragma unroll
        for (int h = 0; h < 2; ++h) {
            uint4 qa = chunk[h];        // A words: elems h*16 .. h*16+15
            uint4 qb = chunk[2 + h];    // B words: elems 32+h*16 ..
            unsigned WAh[4] = {qa.x, qa.y, qa.z, qa.w};
            unsigned WBh[4] = {qb.x, qb.y, qb.z, qb.w};
            #pragma unroll
            for (int w = 0; w < 4; ++w) {
                unsigned wa = WAh[w], wb = WBh[w];
                #pragma unroll
                for (int k = 0; k < 4; ++k) {
                    unsigned pr = __byte_perm(wa, wb, 0x0400 + k * 0x0101);
                    unsigned v  = (pr & BMSK) | BIAS;     // {1024+va, 1024+vb}
                    unsigned mR = heq2_mask(v, p1h);
                    unsigned mI = hgt2_mask(v, p1h);
                    unsigned mP = heq2_mask(v, p2h);
                    unsigned mN = hne2_mask(v, BIAS);
                    accR = __vsub2(accR, mR);
                    accI = __vsub2(accI, mI);
                    accP = __vsub2(accP, mP);
                    accN = __vsub2(accN, mN);
                    p2h = (p1h & mN) | (p2h & ~mN);
                    p1h = (v   & mN) | (p1h & ~mN);
                }
            }
        }

        // ---- reduce 4 chunk lanes (u16 lanes, max 256: no overflow) ----
        #pragma unroll
        for (int m = 1; m <= 2; m <<= 1) {
            accR = __vadd2(accR, __shfl_xor_sync(0xffffffffu, accR, m));
            accI = __vadd2(accI, __shfl_xor_sync(0xffffffffu, accI, m));
            accP = __vadd2(accP, __shfl_xor_sync(0xffffffffu, accP, m));
            accN = __vadd2(accN, __shfl_xor_sync(0xffffffffu, accN, m));
        }

        if (c == 0) {
            int REP = (int)(accR & 0xffffu) + (int)(accR >> 16);
            int INC = (int)(accI & 0xffffu) + (int)(accI >> 16);
            int PER = (int)(accP & 0xffffu) + (int)(accP >> 16);
            int N   = (int)(accN & 0xffffu) + (int)(accN >> 16);
            float o0 = 0.f, o1 = 0.f, o2 = 0.f, o3 = 0.f;
            if (N > 1) {
                int DEC  = (N - 1) - REP - INC;
                float d1 = 1.0f / (float)(N - 1);
                o0 = (float)REP * d1;
                o1 = (float)INC * d1;
                o2 = (float)DEC * d1;
                if (N >= 4) o3 = (float)PER / (float)(N - 2);
            }
            out[(long long)t * ROWS_TILE + (tid >> 2)] =
                make_float4(o0, o1, o2, o3);
        }
        // next iteration's pre-repack __syncthreads orders scan reads of
        // `packed` against the next repack's writes.
    }
}

extern "C" void kernel_launch(void* const* d_in, const int* in_sizes, int n_in,
                              void* d_out, int out_size)
{
    const int4* x = (const int4*)d_in[0];
    float4* out   = (float4*)d_out;
    const int total_elems = in_sizes[0];            // B * L
    const int nrows       = total_elems / L_LEN;    // 131072
    const int total_tiles = nrows / ROWS_TILE;      // 8192
    const int grid = (total_tiles < GRID) ? total_tiles : GRID;
    pattern_kernel<<<grid, TPB, SMEM_TOTAL>>>(x, out, total_tiles);
}